// round 1
// baseline (speedup 1.0000x reference)
#include <cuda_runtime.h>
#include <cuda_bf16.h>
#include <math.h>

// Quantum circuit: 4 qubits, RY(x) encoding + 6 BasicEntangler layers (RX + CNOT ring),
// outputs <Z_q>.
//
// Math: final <Z_q> = v^T S_q v  with v = product state from RY (real),
// S_q = Re(U^dag D_q U), U = fixed entangler unitary (depends only on weights).
// Per-qubit pair products expand in basis (1, cos x, sin x):
//   c^2=(1+C)/2, s^2=(1-C)/2, cs=S/2   (half-angle -> full-angle)
// => out_q = sum over 81 tensor-basis terms of coef[t][q] * prod_g.

#define NQ 4
#define DIM 16
#define NL 6

__device__ __align__(16) float4 g_coef[81];   // [t] -> (out0..out3) coefficients

// m[i][j][basis]: expansion of r(i)*r(j) in basis (1, C, S)
__constant__ float c_m[2][2][3] = {
    { {0.5f, 0.5f, 0.0f}, {0.0f, 0.0f, 0.5f} },
    { {0.0f, 0.0f, 0.5f}, {0.5f, -0.5f, 0.0f} }
};

// ---------------------------------------------------------------------------
// Setup kernel: build U (16 columns, one per thread), then S_q, then coef table.
// One block, 352 threads. Runs once per launch; must be fast (~few us).
// ---------------------------------------------------------------------------
__global__ void setup_kernel(const float* __restrict__ w) {
    __shared__ float Ure[16][16];   // U[b][j]
    __shared__ float Uim[16][16];
    __shared__ float Sq[4][16][16];

    int tid = threadIdx.x;

    if (tid < 16) {
        float re[16], im[16];
        #pragma unroll
        for (int b = 0; b < 16; b++) { re[b] = 0.0f; im[b] = 0.0f; }
        re[tid] = 1.0f;

        for (int l = 0; l < NL; l++) {
            // RX(w[l][q]) on each wire
            #pragma unroll
            for (int q = 0; q < 4; q++) {
                float t = 0.5f * w[l * 4 + q];
                float ct = cosf(t);
                float st = sinf(t);
                int mask = 8 >> q;   // qubit 0 = MSB of the 4-bit index
                #pragma unroll
                for (int b = 0; b < 16; b++) {
                    if (b & mask) continue;
                    int p = b | mask;
                    float r0 = re[b], i0 = im[b], r1 = re[p], i1 = im[p];
                    // RX: [[ct, -i st], [-i st, ct]]
                    re[b] = ct * r0 + st * i1;
                    im[b] = ct * i0 - st * r1;
                    re[p] = ct * r1 + st * i0;
                    im[p] = ct * i1 - st * r0;
                }
            }
            // CNOT ring: (0->1),(1->2),(2->3),(3->0)
            #pragma unroll
            for (int q = 0; q < 4; q++) {
                int c  = q;
                int tq = (q + 1) & 3;
                int cm = 8 >> c;
                int tm = 8 >> tq;
                #pragma unroll
                for (int b = 0; b < 16; b++) {
                    if (!(b & cm)) continue;
                    if (b & tm) continue;
                    int p = b | tm;
                    float tr = re[b]; re[b] = re[p]; re[p] = tr;
                    float ti = im[b]; im[b] = im[p]; im[p] = ti;
                }
            }
        }
        #pragma unroll
        for (int b = 0; b < 16; b++) { Ure[b][tid] = re[b]; Uim[b][tid] = im[b]; }
    }
    __syncthreads();

    // Sq[q][i][j] = sum_b z_q(b) * (Ure[b][i]*Ure[b][j] + Uim[b][i]*Uim[b][j])
    for (int e = tid; e < 4 * 256; e += blockDim.x) {
        int q = e >> 8;
        int i = (e >> 4) & 15;
        int j = e & 15;
        int mask = 8 >> q;
        float s = 0.0f;
        #pragma unroll
        for (int b = 0; b < 16; b++) {
            float zz = (b & mask) ? -1.0f : 1.0f;
            s += zz * (Ure[b][i] * Ure[b][j] + Uim[b][i] * Uim[b][j]);
        }
        Sq[q][i][j] = s;
    }
    __syncthreads();

    // coef[t][q] = sum_{i,j} Sq[q][i][j] * prod_w m[i_w][j_w][t_w]
    // t = ((t0*3 + t1)*3 + t2)*3 + t3
    for (int e = tid; e < 81 * 4; e += blockDim.x) {
        int q = e & 3;
        int t = e >> 2;
        int t3 = t % 3;
        int t2 = (t / 3) % 3;
        int t1 = (t / 9) % 3;
        int t0 = (t / 27) % 3;
        float acc = 0.0f;
        for (int i = 0; i < 16; i++) {
            for (int j = 0; j < 16; j++) {
                float p = c_m[(i >> 3) & 1][(j >> 3) & 1][t0]
                        * c_m[(i >> 2) & 1][(j >> 2) & 1][t1]
                        * c_m[(i >> 1) & 1][(j >> 1) & 1][t2]
                        * c_m[ i       & 1][ j       & 1][t3];
                acc = fmaf(Sq[q][i][j], p, acc);
            }
        }
        ((float*)g_coef)[t * 4 + q] = acc;
    }
}

// ---------------------------------------------------------------------------
// Main kernel: one thread = one sample.
// ---------------------------------------------------------------------------
__global__ void __launch_bounds__(256) eval_kernel(const float4* __restrict__ x,
                                                   float4* __restrict__ out,
                                                   int nB) {
    __shared__ float4 sc[81];
    for (int i = threadIdx.x; i < 81; i += blockDim.x) sc[i] = g_coef[i];
    __syncthreads();

    int i = blockIdx.x * blockDim.x + threadIdx.x;
    if (i >= nB) return;

    float4 xv = x[i];
    float C0, S0, C1, S1, C2, S2, C3, S3;
    __sincosf(xv.x, &S0, &C0);
    __sincosf(xv.y, &S1, &C1);
    __sincosf(xv.z, &S2, &C2);
    __sincosf(xv.w, &S3, &C3);

    float t01[9];
    t01[0] = 1.0f;      t01[1] = C1;        t01[2] = S1;
    t01[3] = C0;        t01[4] = C0 * C1;   t01[5] = C0 * S1;
    t01[6] = S0;        t01[7] = S0 * C1;   t01[8] = S0 * S1;

    float t23[9];
    t23[0] = 1.0f;      t23[1] = C3;        t23[2] = S3;
    t23[3] = C2;        t23[4] = C2 * C3;   t23[5] = C2 * S3;
    t23[6] = S2;        t23[7] = S2 * C3;   t23[8] = S2 * S3;

    float a0 = 0.0f, a1 = 0.0f, a2 = 0.0f, a3 = 0.0f;
    #pragma unroll
    for (int a = 0; a < 9; a++) {
        #pragma unroll
        for (int b = 0; b < 9; b++) {
            float t = t01[a] * t23[b];
            float4 c = sc[a * 9 + b];
            a0 = fmaf(t, c.x, a0);
            a1 = fmaf(t, c.y, a1);
            a2 = fmaf(t, c.z, a2);
            a3 = fmaf(t, c.w, a3);
        }
    }
    out[i] = make_float4(a0, a1, a2, a3);
}

extern "C" void kernel_launch(void* const* d_in, const int* in_sizes, int n_in,
                              void* d_out, int out_size) {
    // metadata order: x [B,4] f32, weights [6,4] f32 — identify by size for safety
    const float* x = (const float*)d_in[0];
    const float* w = (const float*)d_in[1];
    int nx = in_sizes[0];
    if (in_sizes[0] == NL * NQ && n_in > 1) {   // swapped
        x = (const float*)d_in[1];
        w = (const float*)d_in[0];
        nx = in_sizes[1];
    }
    int B = nx / 4;

    setup_kernel<<<1, 352>>>(w);

    int threads = 256;
    int blocks = (B + threads - 1) / threads;
    eval_kernel<<<blocks, threads>>>((const float4*)x, (float4*)d_out, B);
}

// round 2
// speedup vs baseline: 1.2469x; 1.2469x over previous
#include <cuda_runtime.h>
#include <cuda_bf16.h>
#include <math.h>

// 4-qubit circuit: RY(x) encoding + 6 BasicEntangler layers -> <Z_q>.
// out_q(x) = sum over 81 tensor-basis terms coef[t][q] * g0(t0)g1(t1)g2(t2)g3(t3),
// g = (1, cos x_q, sin x_q). coef derived once per launch from weights.

#define NQ 4
#define NL 6

// Duplicated coefficient table: [t][ (c0,c0,c1,c1,c2,c2,c3,c3) ] for packed f32x2 FMA.
__device__ __align__(16) float g_coef_dup[81][8];

// ---------------------------------------------------------------------------
// f32x2 packed helpers (PTX-only on Blackwell; ptxas won't auto-fuse)
// ---------------------------------------------------------------------------
__device__ __forceinline__ unsigned long long pk2(float lo, float hi) {
    unsigned long long r;
    asm("mov.b64 %0, {%1, %2};" : "=l"(r) : "f"(lo), "f"(hi));
    return r;
}
__device__ __forceinline__ void upk2(unsigned long long v, float& lo, float& hi) {
    asm("mov.b64 {%0, %1}, %2;" : "=f"(lo), "=f"(hi) : "l"(v));
}
__device__ __forceinline__ unsigned long long mul2(unsigned long long a, unsigned long long b) {
    unsigned long long d;
    asm("mul.rn.f32x2 %0, %1, %2;" : "=l"(d) : "l"(a), "l"(b));
    return d;
}
__device__ __forceinline__ unsigned long long fma2(unsigned long long a, unsigned long long b,
                                                   unsigned long long c) {
    unsigned long long d;
    asm("fma.rn.f32x2 %0, %1, %2, %3;" : "=l"(d) : "l"(a), "l"(b), "l"(c));
    return d;
}

// ---------------------------------------------------------------------------
// Setup: simulate the 16x16 entangler unitary, build S_q = Re(U^dag Z_q U),
// then factored mode-transform to the 81-term basis. One block, ~2us.
// ---------------------------------------------------------------------------
__global__ void setup_kernel(const float* __restrict__ w) {
    __shared__ float Ure[16][16];   // U[b][col]
    __shared__ float Uim[16][16];
    __shared__ float Sq[1024];      // [q][i][j]
    __shared__ float bufA[768];
    __shared__ float bufB[576];

    int tid = threadIdx.x;

    if (tid < 16) {
        float re[16], im[16];
        #pragma unroll
        for (int b = 0; b < 16; b++) { re[b] = 0.0f; im[b] = 0.0f; }
        re[tid] = 1.0f;

        for (int l = 0; l < NL; l++) {
            #pragma unroll
            for (int q = 0; q < 4; q++) {
                float t = 0.5f * w[l * 4 + q];
                float ct, st;
                __sincosf(t, &st, &ct);
                int mask = 8 >> q;   // qubit 0 = MSB
                #pragma unroll
                for (int b = 0; b < 16; b++) {
                    if (b & mask) continue;
                    int p = b | mask;
                    float r0 = re[b], i0 = im[b], r1 = re[p], i1 = im[p];
                    // RX: [[ct, -i st], [-i st, ct]]
                    re[b] = ct * r0 + st * i1;
                    im[b] = ct * i0 - st * r1;
                    re[p] = ct * r1 + st * i0;
                    im[p] = ct * i1 - st * r0;
                }
            }
            #pragma unroll
            for (int q = 0; q < 4; q++) {
                int cm = 8 >> q;
                int tm = 8 >> ((q + 1) & 3);
                #pragma unroll
                for (int b = 0; b < 16; b++) {
                    if (!(b & cm)) continue;
                    if (b & tm) continue;
                    int p = b | tm;
                    float tr = re[b]; re[b] = re[p]; re[p] = tr;
                    float ti = im[b]; im[b] = im[p]; im[p] = ti;
                }
            }
        }
        #pragma unroll
        for (int b = 0; b < 16; b++) { Ure[b][tid] = re[b]; Uim[b][tid] = im[b]; }
    }
    __syncthreads();

    // Sq[q][i][j] = sum_b z_q(b) * (Ure[b][i]Ure[b][j] + Uim[b][i]Uim[b][j])
    for (int e = tid; e < 1024; e += blockDim.x) {
        int q = e >> 8;
        int i = (e >> 4) & 15;
        int j = e & 15;
        int mask = 8 >> q;
        float s = 0.0f;
        #pragma unroll
        for (int b = 0; b < 16; b++) {
            float zz = (b & mask) ? -1.0f : 1.0f;
            s += zz * (Ure[b][i] * Ure[b][j] + Uim[b][i] * Uim[b][j]);
        }
        Sq[e] = s;
    }
    __syncthreads();

    // Factored transform: contract one qubit pair-index (i_w, j_w) -> t_w per stage.
    // Pair basis map: t=0: 0.5*(S00+S11); t=1: 0.5*(S00-S11); t=2: 0.5*(S01+S10).
    const int pow3[4] = {1, 3, 9, 27};
    const float* in = Sq;
    float* out = bufA;
    for (int s = 0; s < 4; s++) {
        int R = 8 >> s;          // remaining sub-dim after this stage
        int T = pow3[s];         // prefix count
        int D = 2 * R;
        int outN = 4 * T * 3 * R * R;
        for (int e = tid; e < outN; e += blockDim.x) {
            int j2 = e % R;
            int i2 = (e / R) % R;
            int t  = (e / (R * R)) % 3;
            int tp = (e / (R * R * 3)) % T;
            int q  = e / (R * R * 3 * T);
            const float* base = in + (q * T + tp) * D * D;
            float v;
            if (t == 0)      v = 0.5f * (base[i2 * D + j2] + base[(i2 + R) * D + (j2 + R)]);
            else if (t == 1) v = 0.5f * (base[i2 * D + j2] - base[(i2 + R) * D + (j2 + R)]);
            else             v = 0.5f * (base[i2 * D + j2 + R] + base[(i2 + R) * D + j2]);
            out[(((q * T + tp) * 3 + t) * R + i2) * R + j2] = v;
        }
        __syncthreads();
        in = out;
        out = (out == bufA) ? bufB : bufA;
    }
    // 'in' now holds [q][81] (q*81 + t). Emit duplicated layout [t][q*2 .. q*2+1].
    for (int e = tid; e < 324; e += blockDim.x) {
        int q = e / 81;
        int t = e % 81;
        float v = in[e];
        g_coef_dup[t][q * 2]     = v;
        g_coef_dup[t][q * 2 + 1] = v;
    }
}

// ---------------------------------------------------------------------------
// Eval: one thread = two samples, packed f32x2 arithmetic.
// ---------------------------------------------------------------------------
__global__ void __launch_bounds__(256) eval_kernel(const float4* __restrict__ x,
                                                   float4* __restrict__ out,
                                                   int nPairs, int nB) {
    __shared__ __align__(16) float sc[81][8];
    for (int i = threadIdx.x; i < 162; i += blockDim.x)
        ((float4*)sc)[i] = ((const float4*)g_coef_dup)[i];
    __syncthreads();

    int i = blockIdx.x * blockDim.x + threadIdx.x;
    if (i >= nPairs) return;
    int iA = 2 * i;
    int iB = iA + 1;
    bool hasB = iB < nB;

    float4 xA = x[iA];
    float4 xB = hasB ? x[iB] : xA;

    float C0a, S0a, C1a, S1a, C2a, S2a, C3a, S3a;
    float C0b, S0b, C1b, S1b, C2b, S2b, C3b, S3b;
    __sincosf(xA.x, &S0a, &C0a);  __sincosf(xB.x, &S0b, &C0b);
    __sincosf(xA.y, &S1a, &C1a);  __sincosf(xB.y, &S1b, &C1b);
    __sincosf(xA.z, &S2a, &C2a);  __sincosf(xB.z, &S2b, &C2b);
    __sincosf(xA.w, &S3a, &C3a);  __sincosf(xB.w, &S3b, &C3b);

    unsigned long long C0 = pk2(C0a, C0b), S0 = pk2(S0a, S0b);
    unsigned long long C1 = pk2(C1a, C1b), S1 = pk2(S1a, S1b);
    unsigned long long C2 = pk2(C2a, C2b), S2 = pk2(S2a, S2b);
    unsigned long long C3 = pk2(C3a, C3b), S3 = pk2(S3a, S3b);
    unsigned long long ONE = pk2(1.0f, 1.0f);

    unsigned long long t01[9], t23[9];
    t01[0] = ONE; t01[1] = C1;           t01[2] = S1;
    t01[3] = C0;  t01[4] = mul2(C0, C1); t01[5] = mul2(C0, S1);
    t01[6] = S0;  t01[7] = mul2(S0, C1); t01[8] = mul2(S0, S1);
    t23[0] = ONE; t23[1] = C3;           t23[2] = S3;
    t23[3] = C2;  t23[4] = mul2(C2, C3); t23[5] = mul2(C2, S3);
    t23[6] = S2;  t23[7] = mul2(S2, C3); t23[8] = mul2(S2, S3);

    unsigned long long a0 = 0, a1 = 0, a2 = 0, a3 = 0;
    #pragma unroll
    for (int a = 0; a < 9; a++) {
        #pragma unroll
        for (int b = 0; b < 9; b++) {
            unsigned long long t = mul2(t01[a], t23[b]);
            const ulonglong2* cp = (const ulonglong2*)sc[a * 9 + b];
            ulonglong2 c01 = cp[0];   // (c0,c0),(c1,c1)
            ulonglong2 c23 = cp[1];   // (c2,c2),(c3,c3)
            a0 = fma2(t, c01.x, a0);
            a1 = fma2(t, c01.y, a1);
            a2 = fma2(t, c23.x, a2);
            a3 = fma2(t, c23.y, a3);
        }
    }

    float o0a, o0b, o1a, o1b, o2a, o2b, o3a, o3b;
    upk2(a0, o0a, o0b);
    upk2(a1, o1a, o1b);
    upk2(a2, o2a, o2b);
    upk2(a3, o3a, o3b);

    out[iA] = make_float4(o0a, o1a, o2a, o3a);
    if (hasB) out[iB] = make_float4(o0b, o1b, o2b, o3b);
}

extern "C" void kernel_launch(void* const* d_in, const int* in_sizes, int n_in,
                              void* d_out, int out_size) {
    const float* x = (const float*)d_in[0];
    const float* w = (const float*)d_in[1];
    int nx = in_sizes[0];
    if (in_sizes[0] == NL * NQ && n_in > 1) {   // swapped order safety
        x = (const float*)d_in[1];
        w = (const float*)d_in[0];
        nx = in_sizes[1];
    }
    int B = nx / 4;
    int nPairs = (B + 1) / 2;

    setup_kernel<<<1, 256>>>(w);

    int threads = 256;
    int blocks = (nPairs + threads - 1) / threads;
    eval_kernel<<<blocks, threads>>>((const float4*)x, (float4*)d_out, nPairs, B);
}

// round 3
// speedup vs baseline: 1.4351x; 1.1509x over previous
#include <cuda_runtime.h>
#include <cuda_bf16.h>
#include <math.h>

// 4-qubit circuit: RY(x) encoding + 6 BasicEntangler layers -> <Z_q>.
// out_q(x) = sum over 81 tensor-basis terms coef[t][q] * g0(t0)g1(t1)g2(t2)g3(t3),
// g = (1, cos x_q, sin x_q). coef derived once per launch from weights.

#define NQ 4
#define NL 6
#define NPACK 4            // 4 packs x 2 samples = 8 samples per thread
#define TPB 128

// Duplicated coefficient table: [t][ (c0,c0,c1,c1,c2,c2,c3,c3) ] for packed f32x2 FMA.
__device__ __align__(16) float g_coef_dup[81][8];

// ---------------------------------------------------------------------------
// f32x2 packed helpers (PTX-only on Blackwell; ptxas won't auto-fuse)
// ---------------------------------------------------------------------------
__device__ __forceinline__ unsigned long long pk2(float lo, float hi) {
    unsigned long long r;
    asm("mov.b64 %0, {%1, %2};" : "=l"(r) : "f"(lo), "f"(hi));
    return r;
}
__device__ __forceinline__ void upk2(unsigned long long v, float& lo, float& hi) {
    asm("mov.b64 {%0, %1}, %2;" : "=f"(lo), "=f"(hi) : "l"(v));
}
__device__ __forceinline__ unsigned long long mul2(unsigned long long a, unsigned long long b) {
    unsigned long long d;
    asm("mul.rn.f32x2 %0, %1, %2;" : "=l"(d) : "l"(a), "l"(b));
    return d;
}
__device__ __forceinline__ unsigned long long fma2(unsigned long long a, unsigned long long b,
                                                   unsigned long long c) {
    unsigned long long d;
    asm("fma.rn.f32x2 %0, %1, %2, %3;" : "=l"(d) : "l"(a), "l"(b), "l"(c));
    return d;
}

// ---------------------------------------------------------------------------
// Setup: simulate the 16x16 entangler unitary, build S_q = Re(U^dag Z_q U),
// then factored mode-transform to the 81-term basis. One block.
// ---------------------------------------------------------------------------
__global__ void setup_kernel(const float* __restrict__ w) {
    __shared__ float Ure[16][16];
    __shared__ float Uim[16][16];
    __shared__ float Sq[1024];
    __shared__ float bufA[768];
    __shared__ float bufB[576];

    int tid = threadIdx.x;

    if (tid < 16) {
        float re[16], im[16];
        #pragma unroll
        for (int b = 0; b < 16; b++) { re[b] = 0.0f; im[b] = 0.0f; }
        re[tid] = 1.0f;

        for (int l = 0; l < NL; l++) {
            #pragma unroll
            for (int q = 0; q < 4; q++) {
                float t = 0.5f * w[l * 4 + q];
                float ct, st;
                __sincosf(t, &st, &ct);
                int mask = 8 >> q;   // qubit 0 = MSB
                #pragma unroll
                for (int b = 0; b < 16; b++) {
                    if (b & mask) continue;
                    int p = b | mask;
                    float r0 = re[b], i0 = im[b], r1 = re[p], i1 = im[p];
                    re[b] = ct * r0 + st * i1;
                    im[b] = ct * i0 - st * r1;
                    re[p] = ct * r1 + st * i0;
                    im[p] = ct * i1 - st * r0;
                }
            }
            #pragma unroll
            for (int q = 0; q < 4; q++) {
                int cm = 8 >> q;
                int tm = 8 >> ((q + 1) & 3);
                #pragma unroll
                for (int b = 0; b < 16; b++) {
                    if (!(b & cm)) continue;
                    if (b & tm) continue;
                    int p = b | tm;
                    float tr = re[b]; re[b] = re[p]; re[p] = tr;
                    float ti = im[b]; im[b] = im[p]; im[p] = ti;
                }
            }
        }
        #pragma unroll
        for (int b = 0; b < 16; b++) { Ure[b][tid] = re[b]; Uim[b][tid] = im[b]; }
    }
    __syncthreads();

    for (int e = tid; e < 1024; e += blockDim.x) {
        int q = e >> 8;
        int i = (e >> 4) & 15;
        int j = e & 15;
        int mask = 8 >> q;
        float s = 0.0f;
        #pragma unroll
        for (int b = 0; b < 16; b++) {
            float zz = (b & mask) ? -1.0f : 1.0f;
            s += zz * (Ure[b][i] * Ure[b][j] + Uim[b][i] * Uim[b][j]);
        }
        Sq[e] = s;
    }
    __syncthreads();

    const int pow3[4] = {1, 3, 9, 27};
    const float* in = Sq;
    float* out = bufA;
    for (int s = 0; s < 4; s++) {
        int R = 8 >> s;
        int T = pow3[s];
        int D = 2 * R;
        int outN = 4 * T * 3 * R * R;
        for (int e = tid; e < outN; e += blockDim.x) {
            int j2 = e % R;
            int i2 = (e / R) % R;
            int t  = (e / (R * R)) % 3;
            int tp = (e / (R * R * 3)) % T;
            int q  = e / (R * R * 3 * T);
            const float* base = in + (q * T + tp) * D * D;
            float v;
            if (t == 0)      v = 0.5f * (base[i2 * D + j2] + base[(i2 + R) * D + (j2 + R)]);
            else if (t == 1) v = 0.5f * (base[i2 * D + j2] - base[(i2 + R) * D + (j2 + R)]);
            else             v = 0.5f * (base[i2 * D + j2 + R] + base[(i2 + R) * D + j2]);
            out[(((q * T + tp) * 3 + t) * R + i2) * R + j2] = v;
        }
        __syncthreads();
        in = out;
        out = (out == bufA) ? bufB : bufA;
    }
    for (int e = tid; e < 324; e += blockDim.x) {
        int q = e / 81;
        int t = e % 81;
        float v = in[e];
        g_coef_dup[t][q * 2]     = v;
        g_coef_dup[t][q * 2 + 1] = v;
    }
}

// ---------------------------------------------------------------------------
// Eval: 8 samples per thread (4 f32x2 packs). Coefficient LDS amortized 4x.
// Sample mapping keeps loads/stores coalesced: pack p covers samples
// base + (2p)*TPB + tid  and  base + (2p+1)*TPB + tid.
// ---------------------------------------------------------------------------
__global__ void __launch_bounds__(TPB, 3) eval_kernel(const float4* __restrict__ x,
                                                      float4* __restrict__ out,
                                                      int nB) {
    __shared__ __align__(16) float sc[81][8];
    for (int i = threadIdx.x; i < 162; i += TPB)
        ((float4*)sc)[i] = ((const float4*)g_coef_dup)[i];
    __syncthreads();

    const int base = blockIdx.x * (8 * TPB) + threadIdx.x;

    unsigned long long C0[NPACK], S0[NPACK], C1[NPACK], S1[NPACK];
    unsigned long long t23[NPACK][9];   // index 0 unused (== ONE)
    unsigned long long acc[NPACK][4];
    const unsigned long long ONE = pk2(1.0f, 1.0f);

    int lo[NPACK], hi[NPACK];
    #pragma unroll
    for (int p = 0; p < NPACK; p++) {
        lo[p] = base + (2 * p) * TPB;
        hi[p] = base + (2 * p + 1) * TPB;
        float4 xa = (lo[p] < nB) ? x[lo[p]] : make_float4(0.f, 0.f, 0.f, 0.f);
        float4 xb = (hi[p] < nB) ? x[hi[p]] : make_float4(0.f, 0.f, 0.f, 0.f);

        float c0a, s0a, c1a, s1a, c2a, s2a, c3a, s3a;
        float c0b, s0b, c1b, s1b, c2b, s2b, c3b, s3b;
        __sincosf(xa.x, &s0a, &c0a);  __sincosf(xb.x, &s0b, &c0b);
        __sincosf(xa.y, &s1a, &c1a);  __sincosf(xb.y, &s1b, &c1b);
        __sincosf(xa.z, &s2a, &c2a);  __sincosf(xb.z, &s2b, &c2b);
        __sincosf(xa.w, &s3a, &c3a);  __sincosf(xb.w, &s3b, &c3b);

        C0[p] = pk2(c0a, c0b);  S0[p] = pk2(s0a, s0b);
        C1[p] = pk2(c1a, c1b);  S1[p] = pk2(s1a, s1b);
        unsigned long long C2 = pk2(c2a, c2b), S2 = pk2(s2a, s2b);
        unsigned long long C3 = pk2(c3a, c3b), S3 = pk2(s3a, s3b);

        t23[p][1] = C3;
        t23[p][2] = S3;
        t23[p][3] = C2;
        t23[p][4] = mul2(C2, C3);
        t23[p][5] = mul2(C2, S3);
        t23[p][6] = S2;
        t23[p][7] = mul2(S2, C3);
        t23[p][8] = mul2(S2, S3);

        acc[p][0] = 0; acc[p][1] = 0; acc[p][2] = 0; acc[p][3] = 0;
    }

    #pragma unroll
    for (int i0 = 0; i0 < 3; i0++) {
        #pragma unroll
        for (int i1 = 0; i1 < 3; i1++) {
            const int a = i0 * 3 + i1;
            // u = t01[a] per pack, recomputed (saves 72 regs vs storing t01[9])
            unsigned long long u[NPACK];
            #pragma unroll
            for (int p = 0; p < NPACK; p++) {
                if (i0 == 0)      u[p] = (i1 == 0) ? ONE : ((i1 == 1) ? C1[p] : S1[p]);
                else if (i1 == 0) u[p] = (i0 == 1) ? C0[p] : S0[p];
                else {
                    unsigned long long e0 = (i0 == 1) ? C0[p] : S0[p];
                    unsigned long long e1 = (i1 == 1) ? C1[p] : S1[p];
                    u[p] = mul2(e0, e1);
                }
            }
            #pragma unroll
            for (int b = 0; b < 9; b++) {
                const ulonglong2* cp = (const ulonglong2*)sc[a * 9 + b];
                ulonglong2 c01 = cp[0];
                ulonglong2 c23 = cp[1];
                #pragma unroll
                for (int p = 0; p < NPACK; p++) {
                    unsigned long long t;
                    if (a == 0) t = (b == 0) ? ONE : t23[p][b];
                    else        t = (b == 0) ? u[p] : mul2(u[p], t23[p][b]);
                    acc[p][0] = fma2(t, c01.x, acc[p][0]);
                    acc[p][1] = fma2(t, c01.y, acc[p][1]);
                    acc[p][2] = fma2(t, c23.x, acc[p][2]);
                    acc[p][3] = fma2(t, c23.y, acc[p][3]);
                }
            }
        }
    }

    #pragma unroll
    for (int p = 0; p < NPACK; p++) {
        float o0a, o0b, o1a, o1b, o2a, o2b, o3a, o3b;
        upk2(acc[p][0], o0a, o0b);
        upk2(acc[p][1], o1a, o1b);
        upk2(acc[p][2], o2a, o2b);
        upk2(acc[p][3], o3a, o3b);
        if (lo[p] < nB) out[lo[p]] = make_float4(o0a, o1a, o2a, o3a);
        if (hi[p] < nB) out[hi[p]] = make_float4(o0b, o1b, o2b, o3b);
    }
}

extern "C" void kernel_launch(void* const* d_in, const int* in_sizes, int n_in,
                              void* d_out, int out_size) {
    const float* x = (const float*)d_in[0];
    const float* w = (const float*)d_in[1];
    int nx = in_sizes[0];
    if (in_sizes[0] == NL * NQ && n_in > 1) {   // swapped order safety
        x = (const float*)d_in[1];
        w = (const float*)d_in[0];
        nx = in_sizes[1];
    }
    int B = nx / 4;

    setup_kernel<<<1, 256>>>(w);

    int samplesPerBlock = 8 * TPB;
    int blocks = (B + samplesPerBlock - 1) / samplesPerBlock;
    eval_kernel<<<blocks, TPB>>>((const float4*)x, (float4*)d_out, B);
}